// round 1
// baseline (speedup 1.0000x reference)
#include <cuda_runtime.h>
#include <cstdint>

#define HH 128
#define WHX 128
#define H 256
#define W 256
#define NB 4
#define CF 64
#define KK 51
#define PADK 25
#define HP (H + 2*PADK)   // 306
#define WPP (W + 2*PADK)  // 306
#define HW (H*W)          // 65536

// Scratch buffers (allocation-free: static device globals)
__device__ float g_up[(size_t)NB*CF*H*W];        // upsampled features [b][64][256][256]
__device__ float g_t1[(size_t)4*NB*KK*H*W];      // [k][b][51][256][256]
__device__ float g_t2[(size_t)4*NB*KK*H*W];
__device__ float g_k [(size_t)4*NB*KK*H*W];      // final kernels: k=0:k1v 1:k1h 2:k2v 3:k2h

// ---------------------------------------------------------------------------
// 2x bilinear upsample, align_corners=True
// ---------------------------------------------------------------------------
__global__ void upsample_kernel(const float* __restrict__ x, float* __restrict__ out)
{
    int idx = blockIdx.x * blockDim.x + threadIdx.x;
    if (idx >= NB*CF*H*W) return;
    int wo = idx & (W-1);
    int ho = (idx >> 8) & (H-1);
    int bc = idx >> 16;
    const float s = (float)(HH - 1) / (float)(H - 1);
    float py = ho * s;
    float px = wo * s;
    int y0 = (int)floorf(py); int y1 = min(y0 + 1, HH - 1);
    int x0 = (int)floorf(px); int x1 = min(x0 + 1, WHX - 1);
    float wy = py - (float)y0, wx = px - (float)x0;
    const float* p = x + (size_t)bc * HH * WHX;
    float a = p[y0*WHX + x0], b = p[y0*WHX + x1];
    float c = p[y1*WHX + x0], d = p[y1*WHX + x1];
    float top = a*(1.f-wx) + b*wx;
    float bot = c*(1.f-wx) + d*wx;
    out[idx] = top*(1.f-wy) + bot*wy;
}

// ---------------------------------------------------------------------------
// Direct 3x3 conv + bias + relu, register-tiled.
// Each block: 64x16 output tile, 17 output channels (oc group), one (k, b).
// Each thread: 4 horizontally adjacent pixels x 17 oc = 68 accumulators.
// grid: (W/64, H/16, 4*NB*3)
// ---------------------------------------------------------------------------
template<int CIN, bool IN_PER_K>
__global__ void __launch_bounds__(256, 2)
conv3x3_relu(const float* __restrict__ in, const float* __restrict__ wgt,
             const float* __restrict__ bias, float* __restrict__ out)
{
    const int OCG = 17;
    int z   = blockIdx.z;
    int k   = z / (NB*3);
    int r   = z % (NB*3);
    int b   = r / 3;
    int ocg = r % 3;
    int oc0 = ocg * OCG;
    int gx0 = blockIdx.x * 64;
    int gy0 = blockIdx.y * 16;

    extern __shared__ float sm[];
    float* s_w  = sm;                  // [OCG][CIN][9]
    float* s_in = sm + OCG*CIN*9;      // [18][66]

    int tid = threadIdx.x;

    // stage weights for this oc-group (shared by whole block, broadcast reads)
    const float* wsrc = wgt + ((size_t)k*KK + oc0) * CIN * 9;
    for (int i = tid; i < OCG*CIN*9; i += 256) s_w[i] = wsrc[i];

    const float* ip = in + (size_t)(IN_PER_K ? (k*NB + b) : b) * CIN * HW;

    float acc[OCG][4];
    #pragma unroll
    for (int o = 0; o < OCG; o++) {
        acc[o][0] = 0.f; acc[o][1] = 0.f; acc[o][2] = 0.f; acc[o][3] = 0.f;
    }

    int tx = tid & 15, ty = tid >> 4;

    for (int ic = 0; ic < CIN; ic++) {
        __syncthreads();
        // load 18x66 input tile (halo 1), zero-padded at borders
        const float* cp = ip + (size_t)ic * HW;
        for (int i = tid; i < 18*66; i += 256) {
            int rr = i / 66, cc = i % 66;
            int gy = gy0 - 1 + rr, gx = gx0 - 1 + cc;
            float v = 0.f;
            if (gy >= 0 && gy < H && gx >= 0 && gx < W) v = cp[gy*W + gx];
            s_in[i] = v;
        }
        __syncthreads();

        float vin[3][6];
        #pragma unroll
        for (int rr = 0; rr < 3; rr++)
            #pragma unroll
            for (int cc = 0; cc < 6; cc++)
                vin[rr][cc] = s_in[(ty + rr)*66 + tx*4 + cc];

        const float* wp = s_w + ic * 9;
        #pragma unroll
        for (int o = 0; o < OCG; o++) {
            const float* wo = wp + o * CIN * 9;
            float w0 = wo[0], w1 = wo[1], w2 = wo[2];
            float w3 = wo[3], w4 = wo[4], w5 = wo[5];
            float w6 = wo[6], w7 = wo[7], w8 = wo[8];
            #pragma unroll
            for (int p = 0; p < 4; p++) {
                acc[o][p] += w0*vin[0][p]   + w1*vin[0][p+1] + w2*vin[0][p+2]
                           + w3*vin[1][p]   + w4*vin[1][p+1] + w5*vin[1][p+2]
                           + w6*vin[2][p]   + w7*vin[2][p+1] + w8*vin[2][p+2];
            }
        }
    }

    float* op = out + (size_t)(k*NB + b) * KK * HW;
    int oy = gy0 + ty, ox = gx0 + tx*4;
    #pragma unroll
    for (int o = 0; o < OCG; o++) {
        float bv = bias[k*KK + oc0 + o];
        float4 v;
        v.x = fmaxf(acc[o][0] + bv, 0.f);
        v.y = fmaxf(acc[o][1] + bv, 0.f);
        v.z = fmaxf(acc[o][2] + bv, 0.f);
        v.w = fmaxf(acc[o][3] + bv, 0.f);
        *(float4*)(op + (size_t)(oc0 + o)*HW + oy*W + ox) = v;
    }
}

// ---------------------------------------------------------------------------
// Adaptive separable conv of both padded images + sum.
// out[b,c,y,x] = sum_i kv[i] * sum_j kh[j] * img[y+i, x+j]   (for both images)
// Block: 32x8 output tile. kh[51] held in registers; image tile in SMEM.
// grid: (W/32, H/8, NB), block (32,8)
// ---------------------------------------------------------------------------
__global__ void __launch_bounds__(256)
sepconv_kernel(const float* __restrict__ i1, const float* __restrict__ i2,
               const float* __restrict__ gk, float* __restrict__ out)
{
    int b   = blockIdx.z;
    int gx0 = blockIdx.x * 32;
    int gy0 = blockIdx.y * 8;
    int tx  = threadIdx.x, ty = threadIdx.y;
    int tid = ty * 32 + tx;
    int y = gy0 + ty, x = gx0 + tx;

    __shared__ float s_img[58 * 82];

    float acc[3] = {0.f, 0.f, 0.f};

    #pragma unroll 1
    for (int im = 0; im < 2; im++) {
        const float* ip  = im ? i2 : i1;
        const float* kvp = gk + (((size_t)(im*2 + 0)*NB + b)*KK)*HW + y*W + x;
        const float* khp = gk + (((size_t)(im*2 + 1)*NB + b)*KK)*HW + y*W + x;

        float kh[KK];
        #pragma unroll
        for (int j = 0; j < KK; j++) kh[j] = khp[(size_t)j * HW];

        #pragma unroll
        for (int c = 0; c < 3; c++) {
            const float* cp = ip + ((size_t)b*3 + c) * HP * WPP;
            __syncthreads();
            for (int i = tid; i < 58*82; i += 256) {
                int rr = i / 82, cc = i % 82;
                s_img[i] = cp[(size_t)(gy0 + rr)*WPP + gx0 + cc];
            }
            __syncthreads();

            float a = 0.f;
            #pragma unroll 1
            for (int i = 0; i < KK; i++) {
                const float* rp = s_img + (ty + i)*82 + tx;
                float hs = 0.f;
                #pragma unroll
                for (int j = 0; j < KK; j++) hs += kh[j] * rp[j];
                a += kvp[(size_t)i * HW] * hs;
            }
            acc[c] += a;
        }
    }

    size_t ob = ((size_t)b*3)*HW + (size_t)y*W + x;
    out[ob]        = acc[0];
    out[ob + HW]   = acc[1];
    out[ob + 2*HW] = acc[2];
}

// ---------------------------------------------------------------------------
extern "C" void kernel_launch(void* const* d_in, const int* in_sizes, int n_in,
                              void* d_out, int out_size)
{
    const float* x  = (const float*)d_in[0];
    const float* i1 = (const float*)d_in[1];
    const float* i2 = (const float*)d_in[2];
    const float* W1 = (const float*)d_in[3];
    const float* B1 = (const float*)d_in[4];
    const float* W2 = (const float*)d_in[5];
    const float* B2 = (const float*)d_in[6];
    const float* W3 = (const float*)d_in[7];
    const float* B3 = (const float*)d_in[8];
    float* out = (float*)d_out;

    float* up = nullptr; float* t1 = nullptr; float* t2 = nullptr; float* kk = nullptr;
    cudaGetSymbolAddress((void**)&up, g_up);
    cudaGetSymbolAddress((void**)&t1, g_t1);
    cudaGetSymbolAddress((void**)&t2, g_t2);
    cudaGetSymbolAddress((void**)&kk, g_k);

    // 1) upsample features
    {
        int n = NB*CF*H*W;
        upsample_kernel<<<(n + 255)/256, 256>>>(x, up);
    }

    // 2) three conv stages, all 4 kernel-heads folded into grid.z
    dim3 cgrid(W/64, H/16, 4*NB*3);
    {
        size_t smem = (17*64*9 + 18*66) * sizeof(float);
        conv3x3_relu<64, false><<<cgrid, 256, smem>>>(up, W1, B1, t1);
    }
    {
        size_t smem = (17*51*9 + 18*66) * sizeof(float);
        conv3x3_relu<51, true><<<cgrid, 256, smem>>>(t1, W2, B2, t2);
        conv3x3_relu<51, true><<<cgrid, 256, smem>>>(t2, W3, B3, kk);
    }

    // 3) separable filtering of both images + sum
    {
        dim3 g(W/32, H/8, NB);
        dim3 blk(32, 8);
        sepconv_kernel<<<g, blk>>>(i1, i2, kk, out);
    }
}

// round 2
// speedup vs baseline: 1.2463x; 1.2463x over previous
#include <cuda_runtime.h>
#include <cstdint>

#define HH 128
#define WHX 128
#define H 256
#define W 256
#define NB 4
#define CF 64
#define KK 51
#define PADK 25
#define HP (H + 2*PADK)   // 306
#define WPP (W + 2*PADK)  // 306
#define HW (H*W)          // 65536

typedef unsigned long long ull;

__device__ __forceinline__ ull pack2(float lo, float hi) {
    ull r; asm("mov.b64 %0, {%1, %2};" : "=l"(r) : "f"(lo), "f"(hi)); return r;
}
__device__ __forceinline__ void unpack2(ull v, float& lo, float& hi) {
    asm("mov.b64 {%0, %1}, %2;" : "=f"(lo), "=f"(hi) : "l"(v));
}
__device__ __forceinline__ ull ffma2(ull a, ull b, ull c) {
    ull d; asm("fma.rn.f32x2 %0, %1, %2, %3;" : "=l"(d) : "l"(a), "l"(b), "l"(c)); return d;
}

// Scratch buffers (allocation-free: static device globals)
__device__ float g_up[(size_t)NB*CF*H*W];
__device__ float g_t1[(size_t)4*NB*KK*H*W];
__device__ float g_t2[(size_t)4*NB*KK*H*W];
__device__ float g_k [(size_t)4*NB*KK*H*W];   // k=0:k1v 1:k1h 2:k2v 3:k2h

// ---------------------------------------------------------------------------
// 2x bilinear upsample, align_corners=True
// ---------------------------------------------------------------------------
__global__ void upsample_kernel(const float* __restrict__ x, float* __restrict__ out)
{
    int idx = blockIdx.x * blockDim.x + threadIdx.x;
    if (idx >= NB*CF*H*W) return;
    int wo = idx & (W-1);
    int ho = (idx >> 8) & (H-1);
    int bc = idx >> 16;
    const float s = (float)(HH - 1) / (float)(H - 1);
    float py = ho * s;
    float px = wo * s;
    int y0 = (int)floorf(py); int y1 = min(y0 + 1, HH - 1);
    int x0 = (int)floorf(px); int x1 = min(x0 + 1, WHX - 1);
    float wy = py - (float)y0, wx = px - (float)x0;
    const float* p = x + (size_t)bc * HH * WHX;
    float a = p[y0*WHX + x0], b = p[y0*WHX + x1];
    float c = p[y1*WHX + x0], d = p[y1*WHX + x1];
    float top = a*(1.f-wx) + b*wx;
    float bot = c*(1.f-wx) + d*wx;
    out[idx] = top*(1.f-wy) + bot*wy;
}

// ---------------------------------------------------------------------------
// Direct 3x3 conv + bias + relu using packed f32x2 over OUTPUT-CHANNEL pairs.
// Block: 64x16 output tile, 18 output channels (9 pairs), one (k, b, ocg).
// Each thread: 4 adjacent pixels x 9 oc-pairs = 36 packed accumulators.
// Weights staged in SMEM transposed: [ic][tap(9)][ocpair(9)] float2 so one
// broadcast LDS.64 fetches a weight pair. Input tile double-buffered.
// grid: (W/64, H/16, 4*NB*3)
// ---------------------------------------------------------------------------
template<int CIN, bool IN_PER_K>
__global__ void __launch_bounds__(256, 2)
conv3x3_relu2(const float* __restrict__ in, const float* __restrict__ wgt,
              const float* __restrict__ bias, float* __restrict__ out)
{
    const int OCP = 9;        // oc pairs per group
    const int NGRP = 3;       // 3 groups of 18 cover 51 (pad to 54)
    const int TILE = 18*66;

    int z   = blockIdx.z;
    int k   = z / (NB*NGRP);
    int r2  = z % (NB*NGRP);
    int b   = r2 / NGRP;
    int ocg = r2 % NGRP;
    int oc0 = ocg * 18;
    int gx0 = blockIdx.x * 64;
    int gy0 = blockIdx.y * 16;

    extern __shared__ float sm[];
    float2* s_w2 = (float2*)sm;               // [CIN][9][OCP]
    float*  s_in = sm + (size_t)CIN*9*OCP*2;  // double buffer [2][18*66]

    int tid = threadIdx.x;
    int tx = tid & 15, ty = tid >> 4;

    // stage weights transposed (pair lanes = adjacent output channels)
    const float* wsrc = wgt + (size_t)k*KK*CIN*9;
    for (int i = tid; i < CIN*9*OCP; i += 256) {
        int op  = i % OCP;
        int tap = (i / OCP) % 9;
        int ic  = i / (9*OCP);
        int oc  = oc0 + 2*op;
        float lo = (oc     < KK) ? wsrc[((size_t)oc    *CIN + ic)*9 + tap] : 0.f;
        float hi = (oc + 1 < KK) ? wsrc[((size_t)(oc+1)*CIN + ic)*9 + tap] : 0.f;
        s_w2[i] = make_float2(lo, hi);
    }

    const float* ip = in + (size_t)(IN_PER_K ? (k*NB + b) : b) * CIN * HW;

    ull acc[OCP][4];
    #pragma unroll
    for (int o = 0; o < OCP; o++)
        #pragma unroll
        for (int p = 0; p < 4; p++) acc[o][p] = 0ULL;

    // prologue: load ic=0 tile into buffer 0
    {
        const float* cp = ip;
        for (int i = tid; i < TILE; i += 256) {
            int rr = i / 66, cc = i % 66;
            int gy = gy0 - 1 + rr, gx = gx0 - 1 + cc;
            float v = 0.f;
            if ((unsigned)gy < H && (unsigned)gx < W) v = __ldg(cp + gy*W + gx);
            s_in[i] = v;
        }
    }
    __syncthreads();

    for (int ic = 0; ic < CIN; ic++) {
        // prefetch next ic tile into the other buffer
        if (ic + 1 < CIN) {
            const float* cp = ip + (size_t)(ic+1)*HW;
            float* dst = s_in + ((ic+1)&1)*TILE;
            for (int i = tid; i < TILE; i += 256) {
                int rr = i / 66, cc = i % 66;
                int gy = gy0 - 1 + rr, gx = gx0 - 1 + cc;
                float v = 0.f;
                if ((unsigned)gy < H && (unsigned)gx < W) v = __ldg(cp + gy*W + gx);
                dst[i] = v;
            }
        }

        const float* sb = s_in + (ic&1)*TILE;
        const ull* wq = (const ull*)(s_w2 + (size_t)ic*9*OCP);

        #pragma unroll
        for (int r = 0; r < 3; r++) {
            const float* rowp = sb + (ty + r)*66 + tx*4;
            ull vr[6];
            #pragma unroll
            for (int c2 = 0; c2 < 6; c2++) {
                float v = rowp[c2];
                vr[c2] = pack2(v, v);
            }
            #pragma unroll
            for (int op = 0; op < OCP; op++) {
                ull w0 = wq[(r*3 + 0)*OCP + op];
                ull w1 = wq[(r*3 + 1)*OCP + op];
                ull w2 = wq[(r*3 + 2)*OCP + op];
                #pragma unroll
                for (int p = 0; p < 4; p++) {
                    acc[op][p] = ffma2(w0, vr[p],   acc[op][p]);
                    acc[op][p] = ffma2(w1, vr[p+1], acc[op][p]);
                    acc[op][p] = ffma2(w2, vr[p+2], acc[op][p]);
                }
            }
        }
        __syncthreads();
    }

    // epilogue: bias + relu + store
    float* outp = out + (size_t)(k*NB + b) * KK * HW;
    int oy = gy0 + ty, ox = gx0 + tx*4;
    #pragma unroll
    for (int opi = 0; opi < OCP; opi++) {
        float lo[4], hi[4];
        #pragma unroll
        for (int p = 0; p < 4; p++) unpack2(acc[opi][p], lo[p], hi[p]);
        int oc = oc0 + 2*opi;
        if (oc < KK) {
            float bv = bias[k*KK + oc];
            float4 v4;
            v4.x = fmaxf(lo[0] + bv, 0.f);
            v4.y = fmaxf(lo[1] + bv, 0.f);
            v4.z = fmaxf(lo[2] + bv, 0.f);
            v4.w = fmaxf(lo[3] + bv, 0.f);
            *(float4*)(outp + (size_t)oc*HW + oy*W + ox) = v4;
        }
        if (oc + 1 < KK) {
            float bv = bias[k*KK + oc + 1];
            float4 v4;
            v4.x = fmaxf(hi[0] + bv, 0.f);
            v4.y = fmaxf(hi[1] + bv, 0.f);
            v4.z = fmaxf(hi[2] + bv, 0.f);
            v4.w = fmaxf(hi[3] + bv, 0.f);
            *(float4*)(outp + (size_t)(oc+1)*HW + oy*W + ox) = v4;
        }
    }
}

// ---------------------------------------------------------------------------
// Adaptive separable conv of both padded images + sum, packed f32x2 over taps.
// Each thread: 1 output px. Horizontal taps read as even-aligned LDS.64 pairs
// from SMEM; kh taps packed with a per-thread parity phase so the inner loop
// is uniform across the warp. Vertical accumulation stays packed; one final
// horizontal reduce per (im, c).
// grid: (W/32, H/8, NB), block (32, 8)
// ---------------------------------------------------------------------------
__global__ void __launch_bounds__(256)
sepconv2_kernel(const float* __restrict__ i1, const float* __restrict__ i2,
                const float* __restrict__ gk, float* __restrict__ out)
{
    const int SW = 84;  // smem row stride (even, cols 0..81 valid)
    int b   = blockIdx.z;
    int gx0 = blockIdx.x * 32;
    int gy0 = blockIdx.y * 8;
    int tx  = threadIdx.x, ty = threadIdx.y;
    int tid = ty * 32 + tx;
    int y = gy0 + ty, x = gx0 + tx;
    int q = tx & 1;
    int col0 = tx - q;   // even-aligned window start

    __shared__ __align__(16) float s_img[58 * SW];

    float acc[3] = {0.f, 0.f, 0.f};

    #pragma unroll 1
    for (int im = 0; im < 2; im++) {
        const float* ip  = im ? i2 : i1;
        const float* kvp = gk + (((size_t)(im*2 + 0)*NB + b)*KK)*HW + (size_t)y*W + x;
        const float* khp = gk + (((size_t)(im*2 + 1)*NB + b)*KK)*HW + (size_t)y*W + x;

        // packed kh with parity phase: KP[m] multiplies (v[col0+2m], v[col0+2m+1]),
        // i.e. taps (2m - q, 2m+1 - q)
        ull KP[26];
        #pragma unroll
        for (int m = 0; m < 26; m++) {
            int t0 = 2*m - q, t1 = 2*m + 1 - q;
            float lo = ((unsigned)t0 < KK) ? khp[(size_t)t0 * HW] : 0.f;
            float hi = ((unsigned)t1 < KK) ? khp[(size_t)t1 * HW] : 0.f;
            KP[m] = pack2(lo, hi);
        }

        #pragma unroll 1
        for (int c = 0; c < 3; c++) {
            const float* cp = ip + ((size_t)b*3 + c) * HP * WPP;
            __syncthreads();
            for (int i = tid; i < 58*SW; i += 256) {
                int rr = i / SW, cc = i % SW;
                s_img[i] = (cc < 82) ? cp[(size_t)(gy0 + rr)*WPP + gx0 + cc] : 0.f;
            }
            __syncthreads();

            ull acc2 = 0ULL;
            #pragma unroll 1
            for (int i = 0; i < KK; i++) {
                const ull* rp = (const ull*)(s_img + (ty + i)*SW + col0);
                ull hs = 0ULL;
                #pragma unroll
                for (int m = 0; m < 26; m++) hs = ffma2(KP[m], rp[m], hs);
                float kv = kvp[(size_t)i * HW];
                acc2 = ffma2(pack2(kv, kv), hs, acc2);
            }
            float lo, hi; unpack2(acc2, lo, hi);
            acc[c] += lo + hi;
        }
    }

    size_t ob = ((size_t)b*3)*HW + (size_t)y*W + x;
    out[ob]        = acc[0];
    out[ob + HW]   = acc[1];
    out[ob + 2*HW] = acc[2];
}

// ---------------------------------------------------------------------------
extern "C" void kernel_launch(void* const* d_in, const int* in_sizes, int n_in,
                              void* d_out, int out_size)
{
    const float* x  = (const float*)d_in[0];
    const float* i1 = (const float*)d_in[1];
    const float* i2 = (const float*)d_in[2];
    const float* W1 = (const float*)d_in[3];
    const float* B1 = (const float*)d_in[4];
    const float* W2 = (const float*)d_in[5];
    const float* B2 = (const float*)d_in[6];
    const float* W3 = (const float*)d_in[7];
    const float* B3 = (const float*)d_in[8];
    float* out = (float*)d_out;

    float* up = nullptr; float* t1 = nullptr; float* t2 = nullptr; float* kk = nullptr;
    cudaGetSymbolAddress((void**)&up, g_up);
    cudaGetSymbolAddress((void**)&t1, g_t1);
    cudaGetSymbolAddress((void**)&t2, g_t2);
    cudaGetSymbolAddress((void**)&kk, g_k);

    size_t smem64 = (size_t)64*9*9*sizeof(float2) + 2*18*66*sizeof(float);  // 50976
    size_t smem51 = (size_t)51*9*9*sizeof(float2) + 2*18*66*sizeof(float);  // 42552
    cudaFuncSetAttribute(conv3x3_relu2<64, false>,
                         cudaFuncAttributeMaxDynamicSharedMemorySize, (int)smem64);
    cudaFuncSetAttribute(conv3x3_relu2<51, true>,
                         cudaFuncAttributeMaxDynamicSharedMemorySize, (int)smem51);

    // 1) upsample features
    {
        int n = NB*CF*H*W;
        upsample_kernel<<<(n + 255)/256, 256>>>(x, up);
    }

    // 2) three conv stages
    dim3 cgrid(W/64, H/16, 4*NB*3);
    conv3x3_relu2<64, false><<<cgrid, 256, smem64>>>(up, W1, B1, t1);
    conv3x3_relu2<51, true ><<<cgrid, 256, smem51>>>(t1, W2, B2, t2);
    conv3x3_relu2<51, true ><<<cgrid, 256, smem51>>>(t2, W3, B3, kk);

    // 3) separable filtering of both images + sum
    {
        dim3 g(W/32, H/8, NB);
        dim3 blk(32, 8);
        sepconv2_kernel<<<g, blk>>>(i1, i2, kk, out);
    }
}

// round 3
// speedup vs baseline: 1.9748x; 1.5846x over previous
#include <cuda_runtime.h>
#include <cstdint>

#define HH 128
#define WHX 128
#define H 256
#define W 256
#define NB 4
#define CF 64
#define KK 51
#define PADK 25
#define HP (H + 2*PADK)   // 306
#define WPP (W + 2*PADK)  // 306
#define HW (H*W)          // 65536

typedef unsigned long long ull;

__device__ __forceinline__ ull pack2(float lo, float hi) {
    ull r; asm("mov.b64 %0, {%1, %2};" : "=l"(r) : "f"(lo), "f"(hi)); return r;
}
__device__ __forceinline__ void unpack2(ull v, float& lo, float& hi) {
    asm("mov.b64 {%0, %1}, %2;" : "=f"(lo), "=f"(hi) : "l"(v));
}
__device__ __forceinline__ ull ffma2(ull a, ull b, ull c) {
    ull d; asm("fma.rn.f32x2 %0, %1, %2, %3;" : "=l"(d) : "l"(a), "l"(b), "l"(c)); return d;
}
__device__ __forceinline__ uint32_t smem_u32(const void* p) {
    return (uint32_t)__cvta_generic_to_shared(p);
}
__device__ __forceinline__ void cpa16(uint32_t dst, const void* src, int srcsize) {
    asm volatile("cp.async.cg.shared.global [%0], [%1], 16, %2;\n"
                 :: "r"(dst), "l"(src), "r"(srcsize));
}
__device__ __forceinline__ void cpa8(uint32_t dst, const void* src) {
    asm volatile("cp.async.ca.shared.global [%0], [%1], 8;\n"
                 :: "r"(dst), "l"(src));
}
#define CP_COMMIT() asm volatile("cp.async.commit_group;\n" ::: "memory")
#define CP_WAIT0()  asm volatile("cp.async.wait_group 0;\n" ::: "memory")

// Scratch buffers (allocation-free: static device globals)
__device__ float g_up[(size_t)NB*CF*H*W];
__device__ float g_t1[(size_t)4*NB*KK*H*W];
__device__ float g_t2[(size_t)4*NB*KK*H*W];
__device__ float g_k [(size_t)4*NB*KK*H*W];   // k=0:k1v 1:k1h 2:k2v 3:k2h
// packed weights: [k][grp(3)][ic][tap(9)][ocpair(9)] float2
__device__ float2 g_wp1[(size_t)4*3*CF*81];
__device__ float2 g_wp2[(size_t)4*3*KK*81];
__device__ float2 g_wp3[(size_t)4*3*KK*81];

// ---------------------------------------------------------------------------
// pack weights into oc-pair-major float2 layout (run once per stage, tiny)
// ---------------------------------------------------------------------------
__global__ void pack_weights(const float* __restrict__ wgt, float2* __restrict__ wp, int CIN)
{
    int idx = blockIdx.x * blockDim.x + threadIdx.x;
    int total = 4*3*CIN*81;
    if (idx >= total) return;
    int op  = idx % 9;
    int tap = (idx / 9) % 9;
    int ic  = (idx / 81) % CIN;
    int grp = (idx / (81*CIN)) % 3;
    int k   = idx / (81*CIN*3);
    int oc  = grp*18 + 2*op;
    float lo = (oc     < KK) ? wgt[((size_t)(k*KK + oc    )*CIN + ic)*9 + tap] : 0.f;
    float hi = (oc + 1 < KK) ? wgt[((size_t)(k*KK + oc + 1)*CIN + ic)*9 + tap] : 0.f;
    wp[idx] = make_float2(lo, hi);
}

// ---------------------------------------------------------------------------
// 2x bilinear upsample, align_corners=True
// ---------------------------------------------------------------------------
__global__ void upsample_kernel(const float* __restrict__ x, float* __restrict__ out)
{
    int idx = blockIdx.x * blockDim.x + threadIdx.x;
    if (idx >= NB*CF*H*W) return;
    int wo = idx & (W-1);
    int ho = (idx >> 8) & (H-1);
    int bc = idx >> 16;
    const float s = (float)(HH - 1) / (float)(H - 1);
    float py = ho * s;
    float px = wo * s;
    int y0 = (int)floorf(py); int y1 = min(y0 + 1, HH - 1);
    int x0 = (int)floorf(px); int x1 = min(x0 + 1, WHX - 1);
    float wy = py - (float)y0, wx = px - (float)x0;
    const float* p = x + (size_t)bc * HH * WHX;
    float a = p[y0*WHX + x0], b = p[y0*WHX + x1];
    float c = p[y1*WHX + x0], d = p[y1*WHX + x1];
    float top = a*(1.f-wx) + b*wx;
    float bot = c*(1.f-wx) + d*wx;
    out[idx] = top*(1.f-wy) + bot*wy;
}

// ---------------------------------------------------------------------------
// Direct 3x3 conv + bias + relu, packed f32x2 over oc pairs, cp.async staging.
// Block: 64x16 tile, 18 oc (9 pairs), one (k, b, ocg). Thread: 4 px x 9 pairs.
// Input tile: 18 rows x 72 cols (4-aligned halo), double-buffered, 16B cp.async
// with zero-fill for OOB chunks. Weights streamed linearly via 8B cp.async
// from the pre-packed global layout. One barrier + one wait_group per ic.
// grid: (W/64, H/16, 4*NB*3)
// ---------------------------------------------------------------------------
template<int CIN, bool IN_PER_K>
__global__ void __launch_bounds__(256, 2)
conv3x3_relu3(const float* __restrict__ in, const float2* __restrict__ wpack,
              const float* __restrict__ bias, float* __restrict__ out)
{
    const int OCP = 9;
    const int NGRP = 3;
    const int SROW = 72;
    const int TILE = 18*SROW;
    const int NCHUNK = 18*18;                       // 16B chunks per tile
    const int WOFF = (CIN*162 + 3) & ~3;            // float offset of s_in, 16B aligned

    int z   = blockIdx.z;
    int k   = z / (NB*NGRP);
    int r2  = z % (NB*NGRP);
    int b   = r2 / NGRP;
    int ocg = r2 % NGRP;
    int oc0 = ocg * 18;
    int gx0 = blockIdx.x * 64;
    int gy0 = blockIdx.y * 16;

    extern __shared__ float sm[];
    float2* s_w2 = (float2*)sm;        // [CIN][9][OCP]
    float*  s_in = sm + WOFF;          // [2][18][72]

    int tid = threadIdx.x;
    int tx = tid & 15, ty = tid >> 4;

    // stage packed weights (linear, async)
    {
        const float2* wsrc = wpack + (size_t)(k*NGRP + ocg) * CIN * 81;
        uint32_t wdst = smem_u32(s_w2);
        for (int i = tid; i < CIN*81; i += 256)
            cpa8(wdst + i*8, wsrc + i);
    }

    const float* ip = in + (size_t)(IN_PER_K ? (k*NB + b) : b) * CIN * HW;
    uint32_t sin_base = smem_u32(s_in);

    // prologue: tile for ic=0 into buffer 0
    {
        const float* cp0 = ip;
        for (int i = tid; i < NCHUNK; i += 256) {
            int rr = i / 18, f = i % 18;
            int gy = gy0 - 1 + rr;
            int gx = gx0 - 4 + 4*f;
            bool ok = ((unsigned)gy < H) && (gx >= 0) && (gx < W);
            const float* src = ok ? (cp0 + gy*W + gx) : cp0;
            cpa16(sin_base + (rr*SROW + f*4)*4, src, ok ? 16 : 0);
        }
    }
    CP_COMMIT();

    ull acc[OCP][4];
    #pragma unroll
    for (int o = 0; o < OCP; o++)
        #pragma unroll
        for (int p = 0; p < 4; p++) acc[o][p] = 0ULL;

    for (int ic = 0; ic < CIN; ic++) {
        CP_WAIT0();
        __syncthreads();

        // prefetch next tile (overwrites buffer read two iterations ago)
        if (ic + 1 < CIN) {
            const float* cp1 = ip + (size_t)(ic+1)*HW;
            uint32_t dst = sin_base + ((ic+1)&1)*TILE*4;
            for (int i = tid; i < NCHUNK; i += 256) {
                int rr = i / 18, f = i % 18;
                int gy = gy0 - 1 + rr;
                int gx = gx0 - 4 + 4*f;
                bool ok = ((unsigned)gy < H) && (gx >= 0) && (gx < W);
                const float* src = ok ? (cp1 + gy*W + gx) : cp1;
                cpa16(dst + (rr*SROW + f*4)*4, src, ok ? 16 : 0);
            }
            CP_COMMIT();
        }

        const float* sb = s_in + (ic&1)*TILE;
        const ull* wq = (const ull*)s_w2 + (size_t)ic*81;

        #pragma unroll
        for (int r = 0; r < 3; r++) {
            const float* rowp = sb + (ty + r)*SROW + tx*4 + 3;
            ull vr[6];
            #pragma unroll
            for (int c2 = 0; c2 < 6; c2++) {
                float v = rowp[c2];
                vr[c2] = pack2(v, v);
            }
            #pragma unroll
            for (int op = 0; op < OCP; op++) {
                ull w0 = wq[(r*3 + 0)*OCP + op];
                ull w1 = wq[(r*3 + 1)*OCP + op];
                ull w2 = wq[(r*3 + 2)*OCP + op];
                #pragma unroll
                for (int p = 0; p < 4; p++) {
                    acc[op][p] = ffma2(w0, vr[p],   acc[op][p]);
                    acc[op][p] = ffma2(w1, vr[p+1], acc[op][p]);
                    acc[op][p] = ffma2(w2, vr[p+2], acc[op][p]);
                }
            }
        }
    }

    // epilogue: bias + relu + store
    float* outp = out + (size_t)(k*NB + b) * KK * HW;
    int oy = gy0 + ty, ox = gx0 + tx*4;
    #pragma unroll
    for (int opi = 0; opi < OCP; opi++) {
        float lo[4], hi[4];
        #pragma unroll
        for (int p = 0; p < 4; p++) unpack2(acc[opi][p], lo[p], hi[p]);
        int oc = oc0 + 2*opi;
        if (oc < KK) {
            float bv = bias[k*KK + oc];
            float4 v4;
            v4.x = fmaxf(lo[0] + bv, 0.f);
            v4.y = fmaxf(lo[1] + bv, 0.f);
            v4.z = fmaxf(lo[2] + bv, 0.f);
            v4.w = fmaxf(lo[3] + bv, 0.f);
            *(float4*)(outp + (size_t)oc*HW + oy*W + ox) = v4;
        }
        if (oc + 1 < KK) {
            float bv = bias[k*KK + oc + 1];
            float4 v4;
            v4.x = fmaxf(hi[0] + bv, 0.f);
            v4.y = fmaxf(hi[1] + bv, 0.f);
            v4.z = fmaxf(hi[2] + bv, 0.f);
            v4.w = fmaxf(hi[3] + bv, 0.f);
            *(float4*)(outp + (size_t)(oc+1)*HW + oy*W + ox) = v4;
        }
    }
}

// ---------------------------------------------------------------------------
// Adaptive separable conv of both padded images + sum, packed f32x2 over taps.
// grid: (W/32, H/8, NB), block (32, 8)
// ---------------------------------------------------------------------------
__global__ void __launch_bounds__(256)
sepconv2_kernel(const float* __restrict__ i1, const float* __restrict__ i2,
                const float* __restrict__ gk, float* __restrict__ out)
{
    const int SW = 84;
    int b   = blockIdx.z;
    int gx0 = blockIdx.x * 32;
    int gy0 = blockIdx.y * 8;
    int tx  = threadIdx.x, ty = threadIdx.y;
    int tid = ty * 32 + tx;
    int y = gy0 + ty, x = gx0 + tx;
    int q = tx & 1;
    int col0 = tx - q;

    __shared__ __align__(16) float s_img[58 * SW];

    float acc[3] = {0.f, 0.f, 0.f};

    #pragma unroll 1
    for (int im = 0; im < 2; im++) {
        const float* ip  = im ? i2 : i1;
        const float* kvp = gk + (((size_t)(im*2 + 0)*NB + b)*KK)*HW + (size_t)y*W + x;
        const float* khp = gk + (((size_t)(im*2 + 1)*NB + b)*KK)*HW + (size_t)y*W + x;

        ull KP[26];
        #pragma unroll
        for (int m = 0; m < 26; m++) {
            int t0 = 2*m - q, t1 = 2*m + 1 - q;
            float lo = ((unsigned)t0 < KK) ? khp[(size_t)t0 * HW] : 0.f;
            float hi = ((unsigned)t1 < KK) ? khp[(size_t)t1 * HW] : 0.f;
            KP[m] = pack2(lo, hi);
        }

        #pragma unroll 1
        for (int c = 0; c < 3; c++) {
            const float* cp = ip + ((size_t)b*3 + c) * HP * WPP;
            __syncthreads();
            for (int i = tid; i < 58*SW; i += 256) {
                int rr = i / SW, cc = i % SW;
                s_img[i] = (cc < 82) ? cp[(size_t)(gy0 + rr)*WPP + gx0 + cc] : 0.f;
            }
            __syncthreads();

            ull acc2 = 0ULL;
            #pragma unroll 1
            for (int i = 0; i < KK; i++) {
                const ull* rp = (const ull*)(s_img + (ty + i)*SW + col0);
                ull hs = 0ULL;
                #pragma unroll
                for (int m = 0; m < 26; m++) hs = ffma2(KP[m], rp[m], hs);
                float kv = kvp[(size_t)i * HW];
                acc2 = ffma2(pack2(kv, kv), hs, acc2);
            }
            float lo, hi; unpack2(acc2, lo, hi);
            acc[c] += lo + hi;
        }
    }

    size_t ob = ((size_t)b*3)*HW + (size_t)y*W + x;
    out[ob]        = acc[0];
    out[ob + HW]   = acc[1];
    out[ob + 2*HW] = acc[2];
}

// ---------------------------------------------------------------------------
extern "C" void kernel_launch(void* const* d_in, const int* in_sizes, int n_in,
                              void* d_out, int out_size)
{
    const float* x  = (const float*)d_in[0];
    const float* i1 = (const float*)d_in[1];
    const float* i2 = (const float*)d_in[2];
    const float* W1 = (const float*)d_in[3];
    const float* B1 = (const float*)d_in[4];
    const float* W2 = (const float*)d_in[5];
    const float* B2 = (const float*)d_in[6];
    const float* W3 = (const float*)d_in[7];
    const float* B3 = (const float*)d_in[8];
    float* out = (float*)d_out;

    float* up = nullptr; float* t1 = nullptr; float* t2 = nullptr; float* kk = nullptr;
    float2* wp1 = nullptr; float2* wp2 = nullptr; float2* wp3 = nullptr;
    cudaGetSymbolAddress((void**)&up, g_up);
    cudaGetSymbolAddress((void**)&t1, g_t1);
    cudaGetSymbolAddress((void**)&t2, g_t2);
    cudaGetSymbolAddress((void**)&kk, g_k);
    cudaGetSymbolAddress((void**)&wp1, g_wp1);
    cudaGetSymbolAddress((void**)&wp2, g_wp2);
    cudaGetSymbolAddress((void**)&wp3, g_wp3);

    const int WOFF64 = (64*162 + 3) & ~3;
    const int WOFF51 = (51*162 + 3) & ~3;
    size_t smem64 = (size_t)(WOFF64 + 2*18*72) * sizeof(float);
    size_t smem51 = (size_t)(WOFF51 + 2*18*72) * sizeof(float);
    cudaFuncSetAttribute(conv3x3_relu3<64, false>,
                         cudaFuncAttributeMaxDynamicSharedMemorySize, (int)smem64);
    cudaFuncSetAttribute(conv3x3_relu3<51, true>,
                         cudaFuncAttributeMaxDynamicSharedMemorySize, (int)smem51);

    // 0) pack weights (tiny)
    {
        int t64 = 4*3*64*81, t51 = 4*3*51*81;
        pack_weights<<<(t64 + 255)/256, 256>>>(W1, wp1, 64);
        pack_weights<<<(t51 + 255)/256, 256>>>(W2, wp2, 51);
        pack_weights<<<(t51 + 255)/256, 256>>>(W3, wp3, 51);
    }

    // 1) upsample features
    {
        int n = NB*CF*H*W;
        upsample_kernel<<<(n + 255)/256, 256>>>(x, up);
    }

    // 2) three conv stages
    dim3 cgrid(W/64, H/16, 4*NB*3);
    conv3x3_relu3<64, false><<<cgrid, 256, smem64>>>(up, wp1, B1, t1);
    conv3x3_relu3<51, true ><<<cgrid, 256, smem51>>>(t1, wp2, B2, t2);
    conv3x3_relu3<51, true ><<<cgrid, 256, smem51>>>(t2, wp3, B3, kk);

    // 3) separable filtering of both images + sum
    {
        dim3 g(W/32, H/8, NB);
        dim3 blk(32, 8);
        sepconv2_kernel<<<g, blk>>>(i1, i2, kk, out);
    }
}